// round 16
// baseline (speedup 1.0000x reference)
#include <cuda_runtime.h>
#include <cstdint>

#define TSTEPS 1024
#define BATCH  256
#define INSZ   128
#define HID    512
#define OUTSZ  32
#define GRB    8       // batch rows per group (2 groups per cluster)
#define JT     64      // hidden outputs per CTA
#define CLUSZ  8       // CTAs per cluster
#define THR2   512     // threads per rnn CTA (16 warps)
#define HROW   516     // padded tf32 H row
#define NITER  (2 * TSTEPS)

// scratch (device globals: the sanctioned no-alloc workaround)
__device__ float g_xproj[(size_t)TSTEPS * BATCH * HID];   // 512 MB
__device__ float g_hist[(size_t)TSTEPS * BATCH * HID];    // 512 MB: h_t for all t

// ---------------- packed f32x2 helpers ----------------
__device__ __forceinline__ void fma2(unsigned long long& d,
                                     unsigned long long a,
                                     unsigned long long b) {
    asm("fma.rn.f32x2 %0, %1, %2, %0;" : "+l"(d) : "l"(a), "l"(b));
}
__device__ __forceinline__ unsigned long long splat2(float a) {
    unsigned long long r;
    asm("mov.b64 %0, {%1, %1};" : "=l"(r) : "f"(a));
    return r;
}
__device__ __forceinline__ unsigned long long pk2(float x, float y) {
    unsigned long long r;
    asm("mov.b64 %0, {%1, %2};" : "=l"(r) : "f"(x), "f"(y));
    return r;
}
__device__ __forceinline__ float2 unpk(unsigned long long v) {
    float2 f;
    asm("mov.b64 {%0, %1}, %2;" : "=f"(f.x), "=f"(f.y) : "l"(v));
    return f;
}
__device__ __forceinline__ uint32_t smem_u32(const void* p) {
    uint32_t a;
    asm("{ .reg .u64 t; cvta.to.shared.u64 t, %1; cvt.u32.u64 %0, t; }"
        : "=r"(a) : "l"(p));
    return a;
}
__device__ __forceinline__ void cp16_cg(uint32_t dst_smem, const void* src) {
    asm volatile("cp.async.cg.shared.global [%0], [%1], 16;"
                 :: "r"(dst_smem), "l"(src) : "memory");
}
__device__ __forceinline__ void cp_commit() {
    asm volatile("cp.async.commit_group;" ::: "memory");
}
__device__ __forceinline__ void cp_wait_all() {
    asm volatile("cp.async.wait_group 0;" ::: "memory");
}
// ---------------- tf32 mma helpers ----------------
__device__ __forceinline__ uint32_t to_tf32(float f) {
    uint32_t u;
    asm("cvt.rna.tf32.f32 %0, %1;" : "=r"(u) : "f"(f));
    return u;
}
__device__ __forceinline__ void mma_tf32(float& c0, float& c1, float& c2, float& c3,
                                         uint32_t a0, uint32_t a1, uint32_t a2, uint32_t a3,
                                         uint32_t b0, uint32_t b1) {
    asm volatile("mma.sync.aligned.m16n8k8.row.col.f32.tf32.tf32.f32 "
                 "{%0,%1,%2,%3}, {%4,%5,%6,%7}, {%8,%9}, {%0,%1,%2,%3};"
                 : "+f"(c0), "+f"(c1), "+f"(c2), "+f"(c3)
                 : "r"(a0), "r"(a1), "r"(a2), "r"(a3), "r"(b0), "r"(b1));
}

// ---------------------------------------------------------------------------
// Kernel 1: x_proj[t,b,:] = inputs[t,b,:] @ W_in + b_rec
// ---------------------------------------------------------------------------
__global__ void __launch_bounds__(256, 1)
xproj_kernel(const float* __restrict__ in, const float* __restrict__ Win,
             const float* __restrict__ brec)
{
    extern __shared__ float sm1[];
    float*  As  = sm1;               // [128][132] padded
    float4* As4 = (float4*)As;
    float*  Bs  = sm1 + 128 * 132;   // [128][128]
    float4* Bs4 = (float4*)Bs;

    const int tid = threadIdx.x;
    const int m0  = blockIdx.x * 128;
    const int n0  = blockIdx.y * 128;

    for (int i = tid; i < 4096; i += 256) {
        int m = i >> 5, kq = i & 31;
        As4[m * 33 + kq] = *(const float4*)(in + (size_t)(m0 + m) * INSZ + kq * 4);
    }
    for (int i = tid; i < 4096; i += 256) {
        int k = i >> 5, nq = i & 31;
        Bs4[k * 32 + nq] = *(const float4*)(Win + (size_t)k * HID + n0 + nq * 4);
    }
    __syncthreads();

    const int tx = tid & 15, ty = tid >> 4;
    const int mm = ty * 8,   nn = tx * 8;

    unsigned long long accq[8][4];
#pragma unroll
    for (int i = 0; i < 8; i++)
#pragma unroll
        for (int jj = 0; jj < 4; jj++) accq[i][jj] = 0ULL;

#pragma unroll 4
    for (int k = 0; k < 128; k++) {
        unsigned long long aa[8];
#pragma unroll
        for (int i = 0; i < 8; i++) aa[i] = splat2(As[(mm + i) * 132 + k]);
        const ulonglong2* bq = (const ulonglong2*)(Bs4 + k * 32 + (nn >> 2));
        ulonglong2 bA = bq[0];
        ulonglong2 bB = bq[1];
#pragma unroll
        for (int i = 0; i < 8; i++) {
            fma2(accq[i][0], aa[i], bA.x);
            fma2(accq[i][1], aa[i], bA.y);
            fma2(accq[i][2], aa[i], bB.x);
            fma2(accq[i][3], aa[i], bB.y);
        }
    }

    float4 br0 = *(const float4*)(brec + n0 + nn);
    float4 br1 = *(const float4*)(brec + n0 + nn + 4);
#pragma unroll
    for (int i = 0; i < 8; i++) {
        float2 p0 = unpk(accq[i][0]), p1 = unpk(accq[i][1]);
        float2 p2 = unpk(accq[i][2]), p3 = unpk(accq[i][3]);
        float4 s0 = make_float4(p0.x + br0.x, p0.y + br0.y, p1.x + br0.z, p1.y + br0.w);
        float4 s1 = make_float4(p2.x + br1.x, p2.y + br1.y, p3.x + br1.z, p3.y + br1.w);
        float* dst = g_xproj + (size_t)(m0 + mm + i) * HID + n0 + nn;
        *(float4*)dst       = s0;
        *(float4*)(dst + 4) = s1;
    }
}

// ---------------------------------------------------------------------------
// Kernel 2: persistent recurrence, two-group pipeline. 512 threads, 16 warps.
// grid = 128 CTAs = 16 clusters x 8; cluster c owns batch rows [16c,16c+16)
// split into groups A=[16c,16c+8), B=[16c+8,16c+16). Iteration i advances
// group i&1 to step i>>1. Data for iteration i was published at i-2 and
// released by barrier phase i-1 -> no data wait; next group's h is LDG-
// prefetched between arrive and wait, hiding barrier + L2 latency.
// Warp w = (nh = w&1, ks = w>>1). B-frags 64 regs tf32 (as R15).
// MMA m16 tiles carry 8 valid rows (a1=a0, a3=a2; c2/c3 discarded).
// ---------------------------------------------------------------------------
#define SM_HA    0                     // tf32 H: [8][516] = 4128 words
#define SM_PART  4128                  // [8][8][64] = 4096
#define SM_XP    8224                  // [2][512]  = 1024
#define SM2_WORDS (8224 + 1024 + 16)
#define SM2_BYTES (SM2_WORDS * 4)

__global__ void __cluster_dims__(CLUSZ, 1, 1) __launch_bounds__(THR2, 1)
rnn_kernel(const float* __restrict__ Wrec)
{
    extern __shared__ float sm[];
    uint32_t* hA      = (uint32_t*)(sm + SM_HA);
    float*    sh_part = sm + SM_PART;
    float*    sh_xp   = sm + SM_XP;

    const int tid   = threadIdx.x;
    const int lane  = tid & 31;
    const int warp  = tid >> 5;
    const int nh    = warp & 1;          // n-half (32 j)
    const int ks    = warp >> 1;         // k-segment (64 k)
    const int rank  = blockIdx.x & (CLUSZ - 1);
    const int clu   = blockIdx.x >> 3;
    const int b0    = clu * 2 * GRB;
    const int jbase = rank * JT;

    // ---- B fragments: W^T, tf32, resident (64 regs) ----
    uint32_t Bf[8][4][2];
    {
        const int n4 = lane >> 2;
        const int k4 = lane & 3;
#pragma unroll
        for (int nsub = 0; nsub < 4; nsub++) {
            const float* wr = Wrec
                + (size_t)(jbase + nh * 32 + nsub * 8 + n4) * HID + ks * 64 + k4;
#pragma unroll
            for (int kk = 0; kk < 8; kk++) {
                Bf[kk][nsub][0] = to_tf32(wr[kk * 8]);
                Bf[kk][nsub][1] = to_tf32(wr[kk * 8 + 4]);
            }
        }
    }

    // zero tf32 H (iterations 0,1 compute from H=0)
    for (int i = tid; i < GRB * HROW; i += THR2) hA[i] = 0u;

    // per-group resident state: this thread owns element (b = tid>>6, j = tid&63)
    float h_own[2] = {0.f, 0.f};
    const int sb = tid >> 6;         // state row 0..7
    const int sj = tid & 63;

    // xp prefetch geometry: 128 threads, one float4 each of the [8][64] tile
    const int xr = tid >> 4, xq = tid & 15;
    const uint32_t xp_base = smem_u32(sh_xp);
    // preloop: prefetch xp for iteration 0 (g=0, s=0) into buffer 0
    if (tid < 128)
        cp16_cg(xp_base + (uint32_t)(xr * 64 + xq * 4) * 4,
                g_xproj + (size_t)(b0 + xr) * HID + jbase + xq * 4);
    cp_commit();

    // register-prefetched h for the CURRENT iteration (zeros for i<2)
    float4 hr0 = make_float4(0.f, 0.f, 0.f, 0.f);
    float4 hr1 = hr0;

    for (int i = 0; i < NITER; ++i) {
        const int g = i & 1;
        const int s = i >> 1;

        // ---- stage h into tf32 hA (skip i<2: hA already zero) ----
        if (i >= 2) {
            const int f0 = tid,        r0 = f0 >> 7, c0 = (f0 & 127) * 4;
            const int f1 = tid + THR2, r1 = f1 >> 7, c1 = (f1 & 127) * 4;
            *(uint4*)(hA + r0 * HROW + c0) =
                make_uint4(to_tf32(hr0.x), to_tf32(hr0.y), to_tf32(hr0.z), to_tf32(hr0.w));
            *(uint4*)(hA + r1 * HROW + c1) =
                make_uint4(to_tf32(hr1.x), to_tf32(hr1.y), to_tf32(hr1.z), to_tf32(hr1.w));
        }
        cp_wait_all();            // xp(i) ready in buffer i&1
        __syncthreads();          // hA + xp visible

        // prefetch xp for iteration i+1 into the other buffer
        if (i + 1 < NITER && tid < 128) {
            const int gn = (i + 1) & 1, sn = (i + 1) >> 1;
            cp16_cg(xp_base + (uint32_t)(((i + 1) & 1) * 512 + xr * 64 + xq * 4) * 4,
                    g_xproj + ((size_t)sn * BATCH + b0 + gn * GRB + xr) * HID
                    + jbase + xq * 4);
        }
        cp_commit();

        // ---- recurrent matmul: 8 kk x 4 nsub MMAs, 8 valid rows ----
        {
            float c0[4], c1[4], c2[4], c3[4];
#pragma unroll
            for (int n = 0; n < 4; n++) { c0[n]=0.f; c1[n]=0.f; c2[n]=0.f; c3[n]=0.f; }
            const uint32_t* ap = hA + (lane >> 2) * HROW + ks * 64 + (lane & 3);
#pragma unroll
            for (int kk = 0; kk < 8; kk++) {
                uint32_t a0 = ap[kk * 8];
                uint32_t a2 = ap[kk * 8 + 4];
#pragma unroll
                for (int n = 0; n < 4; n++)
                    mma_tf32(c0[n], c1[n], c2[n], c3[n],
                             a0, a0, a2, a2, Bf[kk][n][0], Bf[kk][n][1]);
            }
            const int bb = lane >> 2;
            const int jj = nh * 32 + (lane & 3) * 2;
#pragma unroll
            for (int n = 0; n < 4; n++)
                *(float2*)&sh_part[(ks * 8 + bb) * 64 + jj + n * 8] =
                    make_float2(c0[n], c1[n]);
        }
        __syncthreads();          // partials ready

        // ---- state update: 1 element per thread ----
        {
            float pre = 0.f;
#pragma unroll
            for (int k = 0; k < 8; k++)
                pre += sh_part[(k * 8 + sb) * 64 + sj];
            float act = pre + sh_xp[(i & 1) * 512 + sb * 64 + sj];
            act = act > 0.f ? act : 0.f;
            float hn = 0.999f * h_own[g] + 0.001f * act;
            h_own[g] = hn;
            g_hist[((size_t)s * BATCH + b0 + g * GRB + sb) * HID + jbase + sj] = hn;
        }

        // ---- arrive (release: publishes this group's h) ----
        asm volatile("barrier.cluster.arrive.aligned;" ::: "memory");

        // ---- prefetch next iteration's h (published at i-1, already released) ----
        if (i >= 1 && i + 1 < NITER) {
            const int gn = (i + 1) & 1, sn = (i + 1) >> 1;
            const float4* hs = (const float4*)
                (g_hist + ((size_t)(sn - 1) * BATCH + b0 + gn * GRB) * HID);
            hr0 = __ldcv(hs + tid);
            hr1 = __ldcv(hs + tid + THR2);
        }

        // ---- wait (acquire) ----
        asm volatile("barrier.cluster.wait.aligned;" ::: "memory");
    }
}

// ---------------------------------------------------------------------------
// Kernel 3: out[t,b,:] = g_hist[t,b,:] @ W_out + b_out  (single pass, 16 cols/thread)
// ---------------------------------------------------------------------------
#define OG_AS    0                         // [128][132] = 16896 words
#define OG_WPK   16896                     // wpack [256][32] u64 = 16384 words
#define OG_BOUT  (16896 + 16384)           // [32]
#define OG_BYTES ((OG_BOUT + 32 + 16) * 4)

__global__ void __launch_bounds__(256, 1)
ogemm_kernel(const float* __restrict__ Wout, const float* __restrict__ bout,
             float* __restrict__ out)
{
    extern __shared__ float smo[];
    float* As = smo + OG_AS;                       // [128][132]
    unsigned long long* wpk = (unsigned long long*)(smo + OG_WPK);
    float* sbout = smo + OG_BOUT;

    const int tid = threadIdx.x;
    const size_t m0 = (size_t)blockIdx.x * 128;

    // wpack[k2*32 + oo] = (W_out[2k2][oo], W_out[2k2+1][oo])
    for (int idx = tid; idx < 256 * 32; idx += 256) {
        int k2 = idx >> 5, oo = idx & 31;
        ((float2*)wpk)[idx] =
            make_float2(Wout[(2 * k2) * OUTSZ + oo], Wout[(2 * k2 + 1) * OUTSZ + oo]);
    }
    if (tid < OUTSZ) sbout[tid] = bout[tid];

    const int r    = tid >> 1;         // row 0..127
    const int half = tid & 1;          // 16-col half

    unsigned long long acc[16];
#pragma unroll
    for (int c = 0; c < 16; c++) acc[c] = 0ULL;

    for (int kc = 0; kc < 4; kc++) {
        __syncthreads();
#pragma unroll
        for (int u = 0; u < 16; u++) {
            int i = tid + 256 * u;
            int row = i >> 5, c4 = (i & 31) * 4;
            *(float4*)&As[row * 132 + c4] =
                *(const float4*)(g_hist + (m0 + row) * HID + kc * 128 + c4);
        }
        __syncthreads();

        const float* ar = As + r * 132;
#pragma unroll 4
        for (int k2 = 0; k2 < 64; k2++) {
            unsigned long long hp = pk2(ar[2 * k2], ar[2 * k2 + 1]);
            const unsigned long long* w =
                wpk + (size_t)(kc * 64 + k2) * 32 + half * 16;
#pragma unroll
            for (int c = 0; c < 16; c++) fma2(acc[c], hp, w[c]);
        }
    }

#pragma unroll
    for (int c = 0; c < 16; c++) {
        float2 u = unpk(acc[c]);
        int col = half * 16 + c;
        out[(m0 + r) * OUTSZ + col] = u.x + u.y + sbout[col];
    }
}

// ---------------------------------------------------------------------------
extern "C" void kernel_launch(void* const* d_in, const int* in_sizes, int n_in,
                              void* d_out, int out_size)
{
    const float* inputs = (const float*)d_in[0];
    const float* Wrec   = (const float*)d_in[1];
    const float* Win    = (const float*)d_in[2];
    const float* brec   = (const float*)d_in[3];
    const float* Wout   = (const float*)d_in[4];
    const float* bout   = (const float*)d_in[5];
    float* out = (float*)d_out;

    const int smem1 = (128 * 132 + 128 * 128) * 4;   // 133120
    cudaFuncSetAttribute(xproj_kernel, cudaFuncAttributeMaxDynamicSharedMemorySize, smem1);
    cudaFuncSetAttribute(rnn_kernel,   cudaFuncAttributeMaxDynamicSharedMemorySize, SM2_BYTES);
    cudaFuncSetAttribute(ogemm_kernel, cudaFuncAttributeMaxDynamicSharedMemorySize, OG_BYTES);

    dim3 g1((TSTEPS * BATCH) / 128, HID / 128);
    xproj_kernel<<<g1, 256, smem1>>>(inputs, Win, brec);

    rnn_kernel<<<128, THR2, SM2_BYTES>>>(Wrec);

    ogemm_kernel<<<(TSTEPS * BATCH) / 128, 256, OG_BYTES>>>(Wout, bout, out);

    (void)in_sizes; (void)n_in; (void)out_size;
}

// round 17
// speedup vs baseline: 1.6062x; 1.6062x over previous
#include <cuda_runtime.h>
#include <cstdint>

#define TSTEPS 1024
#define BATCH  256
#define INSZ   128
#define HID    512
#define OUTSZ  32
#define RB     16      // batch rows per cluster
#define JT     64      // hidden outputs per CTA
#define CLUSZ  8       // CTAs per cluster
#define THR2   512     // threads per rnn CTA (16 warps)
#define HROW   516     // padded tf32 H row (conflict-free frag loads)

// scratch (device globals: the sanctioned no-alloc workaround)
__device__ float g_xproj[(size_t)TSTEPS * BATCH * HID];   // 512 MB
__device__ float g_hist[(size_t)TSTEPS * BATCH * HID];    // 512 MB: h_t for all t

// ---------------- packed f32x2 helpers ----------------
__device__ __forceinline__ void fma2(unsigned long long& d,
                                     unsigned long long a,
                                     unsigned long long b) {
    asm("fma.rn.f32x2 %0, %1, %2, %0;" : "+l"(d) : "l"(a), "l"(b));
}
__device__ __forceinline__ unsigned long long pk2(float x, float y) {
    unsigned long long r;
    asm("mov.b64 %0, {%1, %2};" : "=l"(r) : "f"(x), "f"(y));
    return r;
}
__device__ __forceinline__ float2 unpk(unsigned long long v) {
    float2 f;
    asm("mov.b64 {%0, %1}, %2;" : "=f"(f.x), "=f"(f.y) : "l"(v));
    return f;
}
__device__ __forceinline__ uint32_t smem_u32(const void* p) {
    uint32_t a;
    asm("{ .reg .u64 t; cvta.to.shared.u64 t, %1; cvt.u32.u64 %0, t; }"
        : "=r"(a) : "l"(p));
    return a;
}
__device__ __forceinline__ void cp16_cg(uint32_t dst_smem, const void* src) {
    asm volatile("cp.async.cg.shared.global [%0], [%1], 16;"
                 :: "r"(dst_smem), "l"(src) : "memory");
}
__device__ __forceinline__ void cp_commit() {
    asm volatile("cp.async.commit_group;" ::: "memory");
}
__device__ __forceinline__ void cp_wait_all() {
    asm volatile("cp.async.wait_group 0;" ::: "memory");
}
// ---------------- tf32 mma helpers ----------------
__device__ __forceinline__ uint32_t to_tf32(float f) {
    uint32_t u;
    asm("cvt.rna.tf32.f32 %0, %1;" : "=r"(u) : "f"(f));
    return u;
}
__device__ __forceinline__ void mma_tf32(float& c0, float& c1, float& c2, float& c3,
                                         uint32_t a0, uint32_t a1, uint32_t a2, uint32_t a3,
                                         uint32_t b0, uint32_t b1) {
    asm volatile("mma.sync.aligned.m16n8k8.row.col.f32.tf32.tf32.f32 "
                 "{%0,%1,%2,%3}, {%4,%5,%6,%7}, {%8,%9}, {%0,%1,%2,%3};"
                 : "+f"(c0), "+f"(c1), "+f"(c2), "+f"(c3)
                 : "r"(a0), "r"(a1), "r"(a2), "r"(a3), "r"(b0), "r"(b1));
}

// ---------------------------------------------------------------------------
// Kernel 1 (tf32 MMA): x_proj[m,:] = in[m,:] @ W_in + b_rec
// grid = (2048 M-tiles of 128, 8 N-tiles of 64); block = 256 thr (8 warps).
// Warp w owns n-octet n0 = by*64 + w*8, full K=128: Bf = 32 regs tf32.
// A staged once per block as tf32 smem [128][132] (pad -> lane-distinct banks).
// ---------------------------------------------------------------------------
__global__ void __launch_bounds__(256, 1)
xproj_kernel(const float* __restrict__ in, const float* __restrict__ Win,
             const float* __restrict__ brec)
{
    extern __shared__ uint32_t smx[];            // As tf32 [128][132]

    const int tid  = threadIdx.x;
    const int lane = tid & 31;
    const int warp = tid >> 5;
    const size_t m0 = (size_t)blockIdx.x * 128;
    const int n0   = blockIdx.y * 64 + warp * 8;

    // B fragments: Win[k][n] col-frag; b0:(k=lane%4, n=lane/4), b1: k+4
    uint32_t Bf[16][2];
    {
        const int bn = lane >> 2, bk = lane & 3;
        const float* wp = Win + (size_t)bk * HID + n0 + bn;
#pragma unroll
        for (int kk = 0; kk < 16; kk++) {
            Bf[kk][0] = to_tf32(wp[(size_t)(kk * 8) * HID]);
            Bf[kk][1] = to_tf32(wp[(size_t)(kk * 8 + 4) * HID]);
        }
    }
    const int ccol = (lane & 3) * 2;
    const float2 bias = make_float2(brec[n0 + ccol], brec[n0 + ccol + 1]);

    // stage A tile [128][128] -> tf32 smem (coalesced rows)
#pragma unroll
    for (int u = 0; u < 16; u++) {
        int i = tid + 256 * u;
        int row = i >> 5, c4 = (i & 31) * 4;
        float4 v = *(const float4*)(in + (m0 + row) * INSZ + c4);
        *(uint4*)(smx + row * 132 + c4) =
            make_uint4(to_tf32(v.x), to_tf32(v.y), to_tf32(v.z), to_tf32(v.w));
    }
    __syncthreads();

    // 8 m-chunks of 16 rows; 16 MMAs each
#pragma unroll 1
    for (int mc = 0; mc < 8; mc++) {
        const uint32_t* ap = smx + (mc * 16 + (lane >> 2)) * 132 + (lane & 3);
        float c0 = 0.f, c1 = 0.f, c2 = 0.f, c3 = 0.f;
#pragma unroll
        for (int kk = 0; kk < 16; kk++) {
            uint32_t a0 = ap[kk * 8];
            uint32_t a1 = ap[kk * 8 + 8 * 132];
            uint32_t a2 = ap[kk * 8 + 4];
            uint32_t a3 = ap[kk * 8 + 8 * 132 + 4];
            mma_tf32(c0, c1, c2, c3, a0, a1, a2, a3, Bf[kk][0], Bf[kk][1]);
        }
        size_t row = m0 + mc * 16 + (lane >> 2);
        float* dst = g_xproj + row * HID + n0 + ccol;
        *(float2*)dst                      = make_float2(c0 + bias.x, c1 + bias.y);
        *(float2*)(dst + (size_t)8 * HID)  = make_float2(c2 + bias.x, c3 + bias.y);
    }
}

// ---------------------------------------------------------------------------
// Kernel 2: persistent recurrence (R15 structure — best known). 512 thr.
// grid = 128 CTAs = 16 clusters x 8; cluster c owns batch rows [16c,16c+16);
// CTA rank r owns hidden slice [64r, 64r+64).
// Warp w = (nh = w&1, ks = w>>1): n-half (32 j) x k-segment (64 k).
// B-frags: 64 regs tf32. One cluster barrier per step.
// ---------------------------------------------------------------------------
#define SM_HA    0                     // tf32 H: [16][516] = 8256 words
#define SM_PART  8256                  // [8][16][64] = 8192
#define SM_XP    16448                 // [2][16][64] = 2048
#define SM2_WORDS (16448 + 2048 + 16)
#define SM2_BYTES (SM2_WORDS * 4)

__global__ void __cluster_dims__(CLUSZ, 1, 1) __launch_bounds__(THR2, 1)
rnn_kernel(const float* __restrict__ Wrec)
{
    extern __shared__ float sm[];
    uint32_t* hA      = (uint32_t*)(sm + SM_HA);
    float*    sh_part = sm + SM_PART;
    float*    sh_xp   = sm + SM_XP;

    const int tid   = threadIdx.x;
    const int lane  = tid & 31;
    const int warp  = tid >> 5;
    const int nh    = warp & 1;          // n-half (32 j)
    const int ks    = warp >> 1;         // k-segment (64 k)
    const int rank  = blockIdx.x & (CLUSZ - 1);
    const int clu   = blockIdx.x >> 3;
    const int b0    = clu * RB;
    const int jbase = rank * JT;

    // ---- B fragments: W^T, tf32, resident (64 regs) ----
    uint32_t Bf[8][4][2];
    {
        const int n4 = lane >> 2;
        const int k4 = lane & 3;
#pragma unroll
        for (int nsub = 0; nsub < 4; nsub++) {
            const float* wr = Wrec
                + (size_t)(jbase + nh * 32 + nsub * 8 + n4) * HID + ks * 64 + k4;
#pragma unroll
            for (int kk = 0; kk < 8; kk++) {
                Bf[kk][nsub][0] = to_tf32(wr[kk * 8]);
                Bf[kk][nsub][1] = to_tf32(wr[kk * 8 + 4]);
            }
        }
    }

    // zero tf32 H (H_0 = 0)
    for (int i = tid; i < 16 * HROW; i += THR2) hA[i] = 0u;

    // resident state: this thread owns elements (b,j) for idx = tid, tid+512
    float h_own[2] = {0.f, 0.f};

    // xp prefetch geometry: 256 threads each copy one float4 of [16][64]
    const int xb = tid >> 4, xq = tid & 15;
    const float* xsrc0 = g_xproj + (size_t)(b0 + xb) * HID + jbase + xq * 4;
    const uint32_t xp_smem0 = smem_u32(sh_xp) + (uint32_t)(xb * 64 + xq * 4) * 4;
    if (tid < 256) cp16_cg(xp_smem0, xsrc0);
    cp_commit();

    for (int s = 0; s < TSTEPS; ++s) {
        // ---- stage H_s into tf32 smem (s>0: read peers' g_hist[s-1]) ----
        if (s > 0) {
            const float4* hs =
                (const float4*)(g_hist + ((size_t)(s - 1) * BATCH + b0) * HID);
#pragma unroll
            for (int u = 0; u < 4; u++) {
                const int i   = tid + THR2 * u;      // 0..2047 float4 index
                float4 hv = __ldcv(hs + i);
                const int row = i >> 7;
                const int c4  = (i & 127) * 4;
                uint4 tv = make_uint4(to_tf32(hv.x), to_tf32(hv.y),
                                      to_tf32(hv.z), to_tf32(hv.w));
                *(uint4*)(hA + row * HROW + c4) = tv;
            }
        }
        cp_wait_all();            // xp(s) ready in buffer s&1
        __syncthreads();          // sync1: hA + xp visible

        // prefetch xp(s+1)
        if (s + 1 < TSTEPS && tid < 256)
            cp16_cg(xp_smem0 + ((s + 1) & 1) * 4096,
                    xsrc0 + (size_t)(s + 1) * BATCH * HID);
        cp_commit();

        // ---- recurrent matmul: 8 kk x 4 nsub m16n8k8 tf32 MMAs ----
        {
            float c0[4], c1[4], c2[4], c3[4];
#pragma unroll
            for (int n = 0; n < 4; n++) { c0[n]=0.f; c1[n]=0.f; c2[n]=0.f; c3[n]=0.f; }
            const uint32_t* ap = hA + (lane >> 2) * HROW + ks * 64 + (lane & 3);
#pragma unroll
            for (int kk = 0; kk < 8; kk++) {
                uint32_t a0 = ap[kk * 8];
                uint32_t a1 = ap[kk * 8 + 8 * HROW];
                uint32_t a2 = ap[kk * 8 + 4];
                uint32_t a3 = ap[kk * 8 + 8 * HROW + 4];
#pragma unroll
                for (int n = 0; n < 4; n++)
                    mma_tf32(c0[n], c1[n], c2[n], c3[n],
                             a0, a1, a2, a3, Bf[kk][n][0], Bf[kk][n][1]);
            }
            const int bb = lane >> 2;
            const int jj = nh * 32 + (lane & 3) * 2;
#pragma unroll
            for (int n = 0; n < 4; n++) {
                *(float2*)&sh_part[(ks * 16 + bb    ) * 64 + jj + n * 8] =
                    make_float2(c0[n], c1[n]);
                *(float2*)&sh_part[(ks * 16 + bb + 8) * 64 + jj + n * 8] =
                    make_float2(c2[n], c3[n]);
            }
        }
        __syncthreads();          // sync2: partials ready

        // ---- state update: 2 elements per thread, state in registers ----
        {
            const float* xp_cur = sh_xp + (s & 1) * 1024;
            float* gdst = g_hist + ((size_t)s * BATCH + b0) * HID;
#pragma unroll
            for (int u = 0; u < 2; u++) {
                const int idx = tid + THR2 * u;
                const int b = idx >> 6, j = idx & 63;
                float pre = 0.f;
#pragma unroll
                for (int k = 0; k < 8; k++)
                    pre += sh_part[(k * 16 + b) * 64 + j];
                float act = pre + xp_cur[b * 64 + j];
                act = act > 0.f ? act : 0.f;
                float hn = 0.999f * h_own[u] + 0.001f * act;
                h_own[u] = hn;
                gdst[(size_t)b * HID + jbase + j] = hn;
            }
        }
        // cluster barrier: arrive(release) publishes g_hist stores;
        // wait(acquire) + __ldcv on the peer side makes them visible.
        asm volatile("barrier.cluster.arrive.aligned;" ::: "memory");
        asm volatile("barrier.cluster.wait.aligned;"   ::: "memory");
    }
}

// ---------------------------------------------------------------------------
// Kernel 3: out[t,b,:] = g_hist[t,b,:] @ W_out + b_out  (single pass)
// ---------------------------------------------------------------------------
#define OG_AS    0                         // [128][132] = 16896 words
#define OG_WPK   16896                     // wpack [256][32] u64 = 16384 words
#define OG_BOUT  (16896 + 16384)           // [32]
#define OG_BYTES ((OG_BOUT + 32 + 16) * 4)

__global__ void __launch_bounds__(256, 1)
ogemm_kernel(const float* __restrict__ Wout, const float* __restrict__ bout,
             float* __restrict__ out)
{
    extern __shared__ float smo[];
    float* As = smo + OG_AS;                       // [128][132]
    unsigned long long* wpk = (unsigned long long*)(smo + OG_WPK);
    float* sbout = smo + OG_BOUT;

    const int tid = threadIdx.x;
    const size_t m0 = (size_t)blockIdx.x * 128;

    // wpack[k2*32 + oo] = (W_out[2k2][oo], W_out[2k2+1][oo])
    for (int idx = tid; idx < 256 * 32; idx += 256) {
        int k2 = idx >> 5, oo = idx & 31;
        ((float2*)wpk)[idx] =
            make_float2(Wout[(2 * k2) * OUTSZ + oo], Wout[(2 * k2 + 1) * OUTSZ + oo]);
    }
    if (tid < OUTSZ) sbout[tid] = bout[tid];

    const int r    = tid >> 1;         // row 0..127
    const int half = tid & 1;          // 16-col half

    unsigned long long acc[16];
#pragma unroll
    for (int c = 0; c < 16; c++) acc[c] = 0ULL;

    for (int kc = 0; kc < 4; kc++) {
        __syncthreads();
#pragma unroll
        for (int u = 0; u < 16; u++) {
            int i = tid + 256 * u;
            int row = i >> 5, c4 = (i & 31) * 4;
            *(float4*)&As[row * 132 + c4] =
                *(const float4*)(g_hist + (m0 + row) * HID + kc * 128 + c4);
        }
        __syncthreads();

        const float* ar = As + r * 132;
#pragma unroll 4
        for (int k2 = 0; k2 < 64; k2++) {
            unsigned long long hp = pk2(ar[2 * k2], ar[2 * k2 + 1]);
            const unsigned long long* w =
                wpk + (size_t)(kc * 64 + k2) * 32 + half * 16;
#pragma unroll
            for (int c = 0; c < 16; c++) fma2(acc[c], hp, w[c]);
        }
    }

#pragma unroll
    for (int c = 0; c < 16; c++) {
        float2 u = unpk(acc[c]);
        int col = half * 16 + c;
        out[(m0 + r) * OUTSZ + col] = u.x + u.y + sbout[col];
    }
}

// ---------------------------------------------------------------------------
extern "C" void kernel_launch(void* const* d_in, const int* in_sizes, int n_in,
                              void* d_out, int out_size)
{
    const float* inputs = (const float*)d_in[0];
    const float* Wrec   = (const float*)d_in[1];
    const float* Win    = (const float*)d_in[2];
    const float* brec   = (const float*)d_in[3];
    const float* Wout   = (const float*)d_in[4];
    const float* bout   = (const float*)d_in[5];
    float* out = (float*)d_out;

    const int smem1 = 128 * 132 * 4;   // 67584 (tf32 A tile)
    cudaFuncSetAttribute(xproj_kernel, cudaFuncAttributeMaxDynamicSharedMemorySize, smem1);
    cudaFuncSetAttribute(rnn_kernel,   cudaFuncAttributeMaxDynamicSharedMemorySize, SM2_BYTES);
    cudaFuncSetAttribute(ogemm_kernel, cudaFuncAttributeMaxDynamicSharedMemorySize, OG_BYTES);

    dim3 g1((TSTEPS * BATCH) / 128, HID / 64);
    xproj_kernel<<<g1, 256, smem1>>>(inputs, Win, brec);

    rnn_kernel<<<128, THR2, SM2_BYTES>>>(Wrec);

    ogemm_kernel<<<(TSTEPS * BATCH) / 128, 256, OG_BYTES>>>(Wout, bout, out);

    (void)in_sizes; (void)n_in; (void)out_size;
}